// round 2
// baseline (speedup 1.0000x reference)
#include <cuda_runtime.h>
#include <cstdint>

// AggrSum: out[v, :] = sum over rows n with X_node[n] == v of H[n, :]
// H: [N, 64] float32, X_node: [N] int32 (JAX x64 disabled -> int64 becomes int32),
// out: [100000, 64] float32.

constexpr int D = 64;
constexpr int D4 = D / 4;  // float4 chunks per row = 16

__global__ void zero_out_kernel(float4* __restrict__ out, int n4) {
    int i = blockIdx.x * blockDim.x + threadIdx.x;
    int stride = gridDim.x * blockDim.x;
    for (; i < n4; i += stride) {
        out[i] = make_float4(0.f, 0.f, 0.f, 0.f);
    }
}

__global__ void scatter_add_kernel(const float4* __restrict__ H4,
                                   const int* __restrict__ idx,
                                   float* __restrict__ out,
                                   int N) {
    int t = blockIdx.x * blockDim.x + threadIdx.x;
    int row = t >> 4;        // 16 threads cooperate on one row (64 floats)
    int c   = t & 15;        // which float4 of the row
    if (row >= N) return;

    int v = idx[row];                       // broadcast across the 16 threads (L1 hit)
    float4 h = H4[(size_t)row * D4 + c];    // coalesced 16B loads

    float* p = out + (size_t)v * D + (size_t)c * 4;
    // Vector reduction: one 16B L2-side fp32 add, no return value (REDG).
    asm volatile("red.global.add.v4.f32 [%0], {%1, %2, %3, %4};"
                 :: "l"(p), "f"(h.x), "f"(h.y), "f"(h.z), "f"(h.w)
                 : "memory");
}

extern "C" void kernel_launch(void* const* d_in, const int* in_sizes, int n_in,
                              void* d_out, int out_size) {
    const float4* H4  = (const float4*)d_in[0];   // H float32 [N, 64]
    const int*    idx = (const int*)d_in[1];      // X_node int32 [N]
    float*        out = (float*)d_out;            // [V, 64] float32

    int N = in_sizes[1];          // number of rows/messages
    int n4 = out_size / 4;        // out_size = V*D floats

    // 1) Zero the (poisoned) output.
    {
        int threads = 256;
        int blocks = 1024;  // grid-stride
        zero_out_kernel<<<blocks, threads>>>((float4*)out, n4);
    }

    // 2) Scatter-add rows with vectorized L2 reductions.
    {
        int threads = 256;
        long long total = (long long)N * 16;
        int blocks = (int)((total + threads - 1) / threads);
        scatter_add_kernel<<<blocks, threads>>>(H4, idx, out, N);
    }
}